// round 5
// baseline (speedup 1.0000x reference)
#include <cuda_runtime.h>
#include <cuda_bf16.h>

// Problem shape (fixed by the dataset)
#define B_DIM 16
#define S_DIM 2048
#define D_DIM 256
#define ROWS  (B_DIM * S_DIM)          // 32768
#define P_ASEM 0.6f
#define Q_ASEM 0.4f
#define MASK_FILL 1e-9f

// Scratch for projected scores (no cudaMalloc allowed)
__device__ float g_si[ROWS];  // si + bias folded in
__device__ float g_sj[ROWS];

// ---------------------------------------------------------------------------
// Kernel 1: per-row dual dot product (warp per row).
//   si[b,s] = dot(x[b,s,:], W[0:256]) + bias ;  sj[b,s] = dot(x[b,s,:], W[256:512])
// Fires the PDL completion trigger so the fuse kernel's post-sync phase can
// start the moment all proj blocks have stored their results.
// ---------------------------------------------------------------------------
__global__ void proj_kernel(const float* __restrict__ x,
                            const float* __restrict__ W,
                            const float* __restrict__ bias) {
    const int row  = blockIdx.x * (blockDim.x >> 5) + (threadIdx.x >> 5);
    const int lane = threadIdx.x & 31;

    const float4* x4  = reinterpret_cast<const float4*>(x) + (long)row * (D_DIM / 4);
    const float4* Wi4 = reinterpret_cast<const float4*>(W);            // W[0:256]
    const float4* Wj4 = reinterpret_cast<const float4*>(W + D_DIM);    // W[256:512]

    float4 xv0 = x4[lane];
    float4 xv1 = x4[lane + 32];
    float4 wi0 = __ldg(&Wi4[lane]);
    float4 wi1 = __ldg(&Wi4[lane + 32]);
    float4 wj0 = __ldg(&Wj4[lane]);
    float4 wj1 = __ldg(&Wj4[lane + 32]);

    float si = 0.f, sj = 0.f;
    si = fmaf(xv0.x, wi0.x, si); si = fmaf(xv0.y, wi0.y, si);
    si = fmaf(xv0.z, wi0.z, si); si = fmaf(xv0.w, wi0.w, si);
    si = fmaf(xv1.x, wi1.x, si); si = fmaf(xv1.y, wi1.y, si);
    si = fmaf(xv1.z, wi1.z, si); si = fmaf(xv1.w, wi1.w, si);
    sj = fmaf(xv0.x, wj0.x, sj); sj = fmaf(xv0.y, wj0.y, sj);
    sj = fmaf(xv0.z, wj0.z, sj); sj = fmaf(xv0.w, wj0.w, sj);
    sj = fmaf(xv1.x, wj1.x, sj); sj = fmaf(xv1.y, wj1.y, sj);
    sj = fmaf(xv1.z, wj1.z, sj); sj = fmaf(xv1.w, wj1.w, sj);

#pragma unroll
    for (int off = 16; off > 0; off >>= 1) {
        si += __shfl_down_sync(0xFFFFFFFFu, si, off);
        sj += __shfl_down_sync(0xFFFFFFFFu, sj, off);
    }
    if (lane == 0) {
        g_si[row] = si + __ldg(bias);
        g_sj[row] = sj;
    }

    // Release PDL-dependent work in fuse_kernel as early as possible.
    cudaTriggerProgrammaticLaunchCompletion();
}

// ---------------------------------------------------------------------------
// Kernel 2: fused elementwise, 4 rows per block (same batch -> shared column
// vectors). PDL-structured:
//   pre-sync : fill stores for masked rows (no proj dependency) +
//              adj prefetch for unmasked rows + column-mask loads
//   sync     : cudaGridDependencySynchronize() (waits on proj completion)
//   post-sync: g_si / g_sj reads, sigmoid blend, streaming stores
// ---------------------------------------------------------------------------
#define RPB 4   // rows per block

__device__ __forceinline__ float sig_blend(float si, float sjv, int m, float a) {
    float z = si + sjv;
    float s = __fdividef(1.f, 1.f + __expf(-z));
    return m ? fmaf(P_ASEM, s, Q_ASEM * a) : MASK_FILL;
}

__global__ __launch_bounds__(256) void fuse_kernel(const float4* __restrict__ adj4,
                                                   const int*    __restrict__ mask,
                                                   float4*       __restrict__ out4) {
    const unsigned tid   = threadIdx.x;
    const unsigned row0  = blockIdx.x * RPB;                 // rows row0..row0+3 (same batch)
    const unsigned base  = row0 << 9;                        // first float4 of the block
    const unsigned cbase = ((row0 >> 11) << 9) + tid;        // sj/mask col float4 index

    // per-row masks (input tensor -> no proj dependency)
    int mi[RPB];
#pragma unroll
    for (int r = 0; r < RPB; ++r) mi[r] = mask[row0 + r];

    // ---- PRE-SYNC WORK ----
    // 1) masked rows: pure fill, 134 MB of writes fully overlapped with proj
    const float4 fill = make_float4(MASK_FILL, MASK_FILL, MASK_FILL, MASK_FILL);
#pragma unroll
    for (int r = 0; r < RPB; ++r) {
        if (!mi[r]) {
            const unsigned o = base + (r << 9) + tid;
            __stcs(&out4[o], fill);
            __stcs(&out4[o + 256], fill);
        }
    }

    // 2) adj prefetch for unmasked rows (read-once streaming loads)
    float4 aA[RPB], aB[RPB];
#pragma unroll
    for (int r = 0; r < RPB; ++r) {
        if (mi[r]) {
            const unsigned o = base + (r << 9) + tid;
            aA[r] = __ldcs(&adj4[o]);
            aB[r] = __ldcs(&adj4[o + 256]);
        }
    }

    // 3) column masks (input tensor)
    const int4* mj4 = reinterpret_cast<const int4*>(mask);
    const int4  mA  = __ldg(&mj4[cbase]);
    const int4  mB  = __ldg(&mj4[cbase + 256]);

    // ---- WAIT FOR proj_kernel ----
    cudaGridDependencySynchronize();

    // ---- POST-SYNC: needs g_si / g_sj ----
    const float4* sj4 = reinterpret_cast<const float4*>(g_sj);
    const float4  sjA = __ldg(&sj4[cbase]);
    const float4  sjB = __ldg(&sj4[cbase + 256]);

#pragma unroll
    for (int r = 0; r < RPB; ++r) {
        if (mi[r]) {
            const unsigned o  = base + (r << 9) + tid;
            const float    si = g_si[row0 + r];
            float4 out;
            out.x = sig_blend(si, sjA.x, mA.x, aA[r].x);
            out.y = sig_blend(si, sjA.y, mA.y, aA[r].y);
            out.z = sig_blend(si, sjA.z, mA.z, aA[r].z);
            out.w = sig_blend(si, sjA.w, mA.w, aA[r].w);
            __stcs(&out4[o], out);

            out.x = sig_blend(si, sjB.x, mB.x, aB[r].x);
            out.y = sig_blend(si, sjB.y, mB.y, aB[r].y);
            out.z = sig_blend(si, sjB.z, mB.z, aB[r].z);
            out.w = sig_blend(si, sjB.w, mB.w, aB[r].w);
            __stcs(&out4[o + 256], out);
        }
    }
}

// ---------------------------------------------------------------------------
// Launch — fuse is launched with Programmatic Stream Serialization so its
// pre-sync phase overlaps proj_kernel's execution.
// Inputs (metadata order): 0:x [16,2048,256] f32, 1:adj [16,2048,2048] f32,
//                          2:mask [16,2048] i32, 3:W [1,512] f32, 4:b [1] f32
// Output: [16,2048,2048] f32
// ---------------------------------------------------------------------------
extern "C" void kernel_launch(void* const* d_in, const int* in_sizes, int n_in,
                              void* d_out, int out_size) {
    const float* x    = (const float*)d_in[0];
    const float* adj  = (const float*)d_in[1];
    const int*   mask = (const int*)d_in[2];
    const float* W    = (const float*)d_in[3];
    const float* bias = (const float*)d_in[4];
    float* out = (float*)d_out;

    // Kernel 1: 32768 rows, 8 warps (8 rows) per block of 256 threads
    proj_kernel<<<ROWS / 8, 256>>>(x, W, bias);

    // Kernel 2 with PDL: one block per 4 output rows -> 8192 blocks
    cudaLaunchConfig_t cfg = {};
    cfg.gridDim  = dim3(ROWS / RPB, 1, 1);
    cfg.blockDim = dim3(256, 1, 1);
    cfg.dynamicSmemBytes = 0;
    cfg.stream = 0;  // same (capture) stream as proj

    cudaLaunchAttribute attrs[1];
    attrs[0].id = cudaLaunchAttributeProgrammaticStreamSerialization;
    attrs[0].val.programmaticStreamSerializationAllowed = 1;
    cfg.attrs = attrs;
    cfg.numAttrs = 1;

    cudaLaunchKernelEx(&cfg, fuse_kernel,
                       reinterpret_cast<const float4*>(adj),
                       mask,
                       reinterpret_cast<float4*>(out));
}

// round 6
// speedup vs baseline: 1.0376x; 1.0376x over previous
#include <cuda_runtime.h>
#include <cuda_bf16.h>

// Problem shape (fixed by the dataset)
#define B_DIM 16
#define S_DIM 2048
#define D_DIM 256
#define ROWS  (B_DIM * S_DIM)          // 32768
#define P_ASEM 0.6f
#define Q_ASEM 0.4f
#define MASK_FILL 1e-9f

// Scratch for projected scores (no cudaMalloc allowed)
__device__ float g_si[ROWS];  // si + bias folded in
__device__ float g_sj[ROWS];

// ---------------------------------------------------------------------------
// Kernel 1 (v2): dual dot products, 4 rows per warp, MLP=8.
//   si[b,s] = dot(x[b,s,:], W[0:256]) + bias ;  sj[b,s] = dot(x[b,s,:], W[256:512])
// All 8 x float4 loads issued before any FMA; weights live in registers
// (L1-resident after the first block).
// ---------------------------------------------------------------------------
#define PROJ_RPW 4   // rows per warp

__global__ __launch_bounds__(256) void proj_kernel(const float* __restrict__ x,
                                                   const float* __restrict__ W,
                                                   const float* __restrict__ bias) {
    const int warp = blockIdx.x * (blockDim.x >> 5) + (threadIdx.x >> 5);
    const int lane = threadIdx.x & 31;
    const int row0 = warp * PROJ_RPW;

    const float4* Wi4 = reinterpret_cast<const float4*>(W);            // W[0:256]
    const float4* Wj4 = reinterpret_cast<const float4*>(W + D_DIM);    // W[256:512]

    // issue all x loads up front (8 independent LDG.128 per thread)
    float4 xv[PROJ_RPW][2];
#pragma unroll
    for (int r = 0; r < PROJ_RPW; ++r) {
        const float4* x4 = reinterpret_cast<const float4*>(x) +
                           (long)(row0 + r) * (D_DIM / 4);
        xv[r][0] = x4[lane];
        xv[r][1] = x4[lane + 32];
    }

    const float4 wi0 = __ldg(&Wi4[lane]);
    const float4 wi1 = __ldg(&Wi4[lane + 32]);
    const float4 wj0 = __ldg(&Wj4[lane]);
    const float4 wj1 = __ldg(&Wj4[lane + 32]);

    float si[PROJ_RPW], sj[PROJ_RPW];
#pragma unroll
    for (int r = 0; r < PROJ_RPW; ++r) {
        float a = 0.f, b2 = 0.f;
        a = fmaf(xv[r][0].x, wi0.x, a); a = fmaf(xv[r][0].y, wi0.y, a);
        a = fmaf(xv[r][0].z, wi0.z, a); a = fmaf(xv[r][0].w, wi0.w, a);
        a = fmaf(xv[r][1].x, wi1.x, a); a = fmaf(xv[r][1].y, wi1.y, a);
        a = fmaf(xv[r][1].z, wi1.z, a); a = fmaf(xv[r][1].w, wi1.w, a);
        b2 = fmaf(xv[r][0].x, wj0.x, b2); b2 = fmaf(xv[r][0].y, wj0.y, b2);
        b2 = fmaf(xv[r][0].z, wj0.z, b2); b2 = fmaf(xv[r][0].w, wj0.w, b2);
        b2 = fmaf(xv[r][1].x, wj1.x, b2); b2 = fmaf(xv[r][1].y, wj1.y, b2);
        b2 = fmaf(xv[r][1].z, wj1.z, b2); b2 = fmaf(xv[r][1].w, wj1.w, b2);
        si[r] = a; sj[r] = b2;
    }

#pragma unroll
    for (int off = 16; off > 0; off >>= 1) {
#pragma unroll
        for (int r = 0; r < PROJ_RPW; ++r) {
            si[r] += __shfl_down_sync(0xFFFFFFFFu, si[r], off);
            sj[r] += __shfl_down_sync(0xFFFFFFFFu, sj[r], off);
        }
    }
    if (lane == 0) {
        const float bv = __ldg(bias);
#pragma unroll
        for (int r = 0; r < PROJ_RPW; ++r) {
            g_si[row0 + r] = si[r] + bv;
            g_sj[row0 + r] = sj[r];
        }
    }
}

// ---------------------------------------------------------------------------
// Kernel 2 (R4 body — known good): fused elementwise, 4 rows per block (same
// batch -> shared column vectors). adj loads for unmasked rows issued up
// front; masked rows write pure fill with zero read traffic.
// ---------------------------------------------------------------------------
#define RPB 4   // rows per block

__device__ __forceinline__ float sig_blend(float si, float sjv, int m, float a) {
    float z = si + sjv;
    float s = __fdividef(1.f, 1.f + __expf(-z));
    return m ? fmaf(P_ASEM, s, Q_ASEM * a) : MASK_FILL;
}

__global__ __launch_bounds__(256) void fuse_kernel(const float4* __restrict__ adj4,
                                                   const int*    __restrict__ mask,
                                                   float4*       __restrict__ out4) {
    const unsigned tid   = threadIdx.x;
    const unsigned row0  = blockIdx.x * RPB;                 // rows row0..row0+3 (same batch)
    const unsigned base  = row0 << 9;                        // first float4 of the block
    const unsigned cbase = ((row0 >> 11) << 9) + tid;        // sj/mask col float4 index

    // per-row masks (uniform across block for each row)
    int mi[RPB];
#pragma unroll
    for (int r = 0; r < RPB; ++r) mi[r] = mask[row0 + r];

    // issue ALL adj loads for unmasked rows up front (predicated, independent)
    float4 aA[RPB], aB[RPB];
#pragma unroll
    for (int r = 0; r < RPB; ++r) {
        if (mi[r]) {
            const unsigned o = base + (r << 9) + tid;
            aA[r] = __ldcs(&adj4[o]);
            aB[r] = __ldcs(&adj4[o + 256]);
        }
    }

    // column vectors: shared by all RPB rows, loaded once
    const float4* sj4 = reinterpret_cast<const float4*>(g_sj);
    const int4*   mj4 = reinterpret_cast<const int4*>(mask);
    const float4 sjA = __ldg(&sj4[cbase]);
    const float4 sjB = __ldg(&sj4[cbase + 256]);
    const int4   mA  = __ldg(&mj4[cbase]);
    const int4   mB  = __ldg(&mj4[cbase + 256]);

#pragma unroll
    for (int r = 0; r < RPB; ++r) {
        const unsigned o = base + (r << 9) + tid;
        if (mi[r]) {
            const float si = g_si[row0 + r];
            float4 out;
            out.x = sig_blend(si, sjA.x, mA.x, aA[r].x);
            out.y = sig_blend(si, sjA.y, mA.y, aA[r].y);
            out.z = sig_blend(si, sjA.z, mA.z, aA[r].z);
            out.w = sig_blend(si, sjA.w, mA.w, aA[r].w);
            __stcs(&out4[o], out);

            out.x = sig_blend(si, sjB.x, mB.x, aB[r].x);
            out.y = sig_blend(si, sjB.y, mB.y, aB[r].y);
            out.z = sig_blend(si, sjB.z, mB.z, aB[r].z);
            out.w = sig_blend(si, sjB.w, mB.w, aB[r].w);
            __stcs(&out4[o + 256], out);
        } else {
            const float4 fill = make_float4(MASK_FILL, MASK_FILL, MASK_FILL, MASK_FILL);
            __stcs(&out4[o], fill);
            __stcs(&out4[o + 256], fill);
        }
    }
}

// ---------------------------------------------------------------------------
// Launch
// Inputs (metadata order): 0:x [16,2048,256] f32, 1:adj [16,2048,2048] f32,
//                          2:mask [16,2048] i32, 3:W [1,512] f32, 4:b [1] f32
// Output: [16,2048,2048] f32
// ---------------------------------------------------------------------------
extern "C" void kernel_launch(void* const* d_in, const int* in_sizes, int n_in,
                              void* d_out, int out_size) {
    const float* x    = (const float*)d_in[0];
    const float* adj  = (const float*)d_in[1];
    const int*   mask = (const int*)d_in[2];
    const float* W    = (const float*)d_in[3];
    const float* bias = (const float*)d_in[4];
    float* out = (float*)d_out;

    // Kernel 1: 4 rows/warp, 8 warps/block -> 32 rows/block -> 1024 blocks
    proj_kernel<<<ROWS / (PROJ_RPW * 8), 256>>>(x, W, bias);

    // Kernel 2: one block per 4 output rows -> 8192 blocks
    fuse_kernel<<<ROWS / RPB, 256>>>(reinterpret_cast<const float4*>(adj),
                                     mask,
                                     reinterpret_cast<float4*>(out));
}